// round 2
// baseline (speedup 1.0000x reference)
#include <cuda_runtime.h>

#define Bz 8
#define Hn 4
#define Ln 256
#define Dn 32

__global__ __launch_bounds__(256, 6)
void taa_kernel(const float* __restrict__ Q, const float* __restrict__ K,
                const float* __restrict__ V, const float* __restrict__ tmK,
                const float* __restrict__ tmV, const float* __restrict__ amask,
                const unsigned char* __restrict__ pad,
                float* __restrict__ x_out, float* __restrict__ attn_out)
{
    __shared__ float sQ[Dn];
    __shared__ float sE[Ln];          // energy, then attn
    __shared__ float wmax[8];
    __shared__ float wsum[8];
    __shared__ float red[32 * Dn];    // 32 k0-groups x 32 d

    const int bid = blockIdx.x;
    const int q = bid & (Ln - 1);
    const int h = (bid >> 8) & (Hn - 1);
    const int b = bid >> 10;

    const int tid  = threadIdx.x;
    const int lane = tid & 31;
    const int wid  = tid >> 5;

    const int bh = b * Hn + h;
    const float* __restrict__ Qrow = Q   + ((size_t)bh * Ln + q) * Dn;
    const float* __restrict__ tmKq = tmK + (((size_t)bh * Ln + q) * Ln) * Dn;
    const float* __restrict__ tmVq = tmV + (((size_t)bh * Ln + q) * Ln) * Dn;
    const float* __restrict__ Kbh  = K + (size_t)bh * Ln * Dn;
    const float* __restrict__ Vbh  = V + (size_t)bh * Ln * Dn;

    if (tid < Dn) sQ[tid] = Qrow[tid];
    __syncthreads();

    const int k0 = tid >> 3;      // 0..31
    const int dq = tid & 7;       // 0..7 (float4 index within D=32)
    const float4 q4 = reinterpret_cast<const float4*>(sQ)[dq];

    // ---------------- Phase 1: energy[k] = (tmK[k,:]+K[k,:]) . Q ----------------
    // tmK is single-use: stream it (evict-first) so L2 keeps K/V/Q hot.
#pragma unroll
    for (int j = 0; j < 8; j++) {
        const int k = k0 + 32 * j;
        const float4 tk = __ldcs(reinterpret_cast<const float4*>(tmKq + (size_t)k * Dn) + dq);
        const float4 kv = __ldg (reinterpret_cast<const float4*>(Kbh  + (size_t)k * Dn) + dq);
        float p = (tk.x + kv.x) * q4.x + (tk.y + kv.y) * q4.y
                + (tk.z + kv.z) * q4.z + (tk.w + kv.w) * q4.w;
        p += __shfl_down_sync(0xffffffffu, p, 4, 8);
        p += __shfl_down_sync(0xffffffffu, p, 2, 8);
        p += __shfl_down_sync(0xffffffffu, p, 1, 8);
        if (dq == 0) sE[k] = p;
    }
    __syncthreads();

    // ---------------- Softmax over k (row of 256) ----------------
    const float inv_scale = 0.17677669529663689f;   // 1/sqrt(32)
    float e = sE[tid] * inv_scale + amask[q * Ln + tid];
    if (pad[b * Ln + tid]) e = -4294967295.0f;      // -2^32 + 1

    float m = e;
#pragma unroll
    for (int o = 16; o > 0; o >>= 1) m = fmaxf(m, __shfl_xor_sync(0xffffffffu, m, o));
    if (lane == 0) wmax[wid] = m;
    __syncthreads();
    m = wmax[0];
#pragma unroll
    for (int i = 1; i < 8; i++) m = fmaxf(m, wmax[i]);

    const float ex = __expf(e - m);
    float s = ex;
#pragma unroll
    for (int o = 16; o > 0; o >>= 1) s += __shfl_xor_sync(0xffffffffu, s, o);
    if (lane == 0) wsum[wid] = s;
    __syncthreads();
    s = wsum[0];
#pragma unroll
    for (int i = 1; i < 8; i++) s += wsum[i];

    const float a = ex * __frcp_rn(s);
    __syncthreads();               // protect sE before overwrite (phase-1 reads done)
    sE[tid] = a;
    __stcs(&attn_out[((size_t)bh * Ln + q) * Ln + tid], a);
    __syncthreads();

    // ---------------- Phase 2: x[d] = sum_k attn[k]*(tmV[k,d]+V[k,d]) ----------------
    float4 acc = make_float4(0.f, 0.f, 0.f, 0.f);
#pragma unroll
    for (int j = 0; j < 8; j++) {
        const int k = k0 + 32 * j;
        const float av = sE[k];
        const float4 tv = __ldcs(reinterpret_cast<const float4*>(tmVq + (size_t)k * Dn) + dq);
        const float4 vv = __ldg (reinterpret_cast<const float4*>(Vbh  + (size_t)k * Dn) + dq);
        acc.x += av * (tv.x + vv.x);
        acc.y += av * (tv.y + vv.y);
        acc.z += av * (tv.z + vv.z);
        acc.w += av * (tv.w + vv.w);
    }
    reinterpret_cast<float4*>(red + k0 * Dn)[dq] = acc;
    __syncthreads();

    if (tid < Dn) {
        float xs = 0.f;
#pragma unroll
        for (int g = 0; g < 32; g++) xs += red[g * Dn + tid];
        __stcs(&x_out[((size_t)bh * Ln + q) * Dn + tid], xs);
    }
}

extern "C" void kernel_launch(void* const* d_in, const int* in_sizes, int n_in,
                              void* d_out, int out_size)
{
    const float* Q    = (const float*)d_in[0];
    const float* K    = (const float*)d_in[1];
    const float* V    = (const float*)d_in[2];
    const float* tmK  = (const float*)d_in[3];
    const float* tmV  = (const float*)d_in[4];
    const float* mask = (const float*)d_in[5];
    const unsigned char* pad = (const unsigned char*)d_in[6];

    float* out  = (float*)d_out;
    float* x    = out;                                // [B,H,L,D]
    float* attn = out + (size_t)Bz * Hn * Ln * Dn;    // [B,H,L,L]

    taa_kernel<<<Bz * Hn * Ln, 256>>>(Q, K, V, tmK, tmV, mask, pad, x, attn);
}

// round 3
// speedup vs baseline: 1.0067x; 1.0067x over previous
#include <cuda_runtime.h>

#define Bz 8
#define Hn 4
#define Ln 256
#define Dn 32

__global__ __launch_bounds__(256)
void taa_kernel(const float* __restrict__ Q, const float* __restrict__ K,
                const float* __restrict__ V, const float* __restrict__ tmK,
                const float* __restrict__ tmV, const float* __restrict__ amask,
                const unsigned char* __restrict__ pad,
                float* __restrict__ x_out, float* __restrict__ attn_out)
{
    __shared__ float sQ[Dn];
    __shared__ float sE[Ln];          // energy, then attn
    __shared__ float wmax[8];
    __shared__ float wsum[8];
    __shared__ float red[32 * Dn];    // 32 k0-groups x 32 d

    const int bid = blockIdx.x;
    const int q = bid & (Ln - 1);
    const int h = (bid >> 8) & (Hn - 1);
    const int b = bid >> 10;

    const int tid  = threadIdx.x;
    const int lane = tid & 31;
    const int wid  = tid >> 5;

    const int bh = b * Hn + h;
    const float* __restrict__ Qrow = Q   + ((size_t)bh * Ln + q) * Dn;
    const float* __restrict__ tmKq = tmK + (((size_t)bh * Ln + q) * Ln) * Dn;
    const float* __restrict__ tmVq = tmV + (((size_t)bh * Ln + q) * Ln) * Dn;
    const float* __restrict__ Kbh  = K + (size_t)bh * Ln * Dn;
    const float* __restrict__ Vbh  = V + (size_t)bh * Ln * Dn;

    if (tid < Dn) sQ[tid] = Qrow[tid];
    __syncthreads();

    const int k0 = tid >> 3;      // 0..31
    const int dq = tid & 7;       // 0..7 (float4 index within D=32)
    const float4 q4 = reinterpret_cast<const float4*>(sQ)[dq];

    // ---------------- Phase 1: energy[k] = (tmK[k,:]+K[k,:]) . Q ----------------
#pragma unroll
    for (int j = 0; j < 8; j++) {
        const int k = k0 + 32 * j;
        const float4 tk = __ldcs(reinterpret_cast<const float4*>(tmKq + (size_t)k * Dn) + dq);
        const float4 kv = __ldg (reinterpret_cast<const float4*>(Kbh  + (size_t)k * Dn) + dq);
        float p = (tk.x + kv.x) * q4.x + (tk.y + kv.y) * q4.y
                + (tk.z + kv.z) * q4.z + (tk.w + kv.w) * q4.w;
        p += __shfl_down_sync(0xffffffffu, p, 4, 8);
        p += __shfl_down_sync(0xffffffffu, p, 2, 8);
        p += __shfl_down_sync(0xffffffffu, p, 1, 8);
        if (dq == 0) sE[k] = p;
    }

    // ---- Prefetch first half of the phase-2 tmV stream (independent of softmax)
    // so DRAM stays active across the softmax barrier bubble. ----
    float4 pf[4];
#pragma unroll
    for (int j = 0; j < 4; j++) {
        const int k = k0 + 32 * j;
        pf[j] = __ldcs(reinterpret_cast<const float4*>(tmVq + (size_t)k * Dn) + dq);
    }

    __syncthreads();

    // ---------------- Softmax over k (row of 256) ----------------
    const float inv_scale = 0.17677669529663689f;   // 1/sqrt(32)
    float e = sE[tid] * inv_scale + amask[q * Ln + tid];
    if (pad[b * Ln + tid]) e = -4294967295.0f;      // -2^32 + 1

    float m = e;
#pragma unroll
    for (int o = 16; o > 0; o >>= 1) m = fmaxf(m, __shfl_xor_sync(0xffffffffu, m, o));
    if (lane == 0) wmax[wid] = m;
    __syncthreads();
    m = wmax[0];
#pragma unroll
    for (int i = 1; i < 8; i++) m = fmaxf(m, wmax[i]);

    const float ex = __expf(e - m);
    float s = ex;
#pragma unroll
    for (int o = 16; o > 0; o >>= 1) s += __shfl_xor_sync(0xffffffffu, s, o);
    if (lane == 0) wsum[wid] = s;
    __syncthreads();
    s = wsum[0];
#pragma unroll
    for (int i = 1; i < 8; i++) s += wsum[i];

    const float a = ex * __frcp_rn(s);
    __syncthreads();               // protect sE before overwrite (phase-1 reads done)
    sE[tid] = a;
    __stcs(&attn_out[((size_t)bh * Ln + q) * Ln + tid], a);
    __syncthreads();

    // ---------------- Phase 2: x[d] = sum_k attn[k]*(tmV[k,d]+V[k,d]) ----------------
    float4 acc = make_float4(0.f, 0.f, 0.f, 0.f);
#pragma unroll
    for (int j = 0; j < 4; j++) {
        const int k = k0 + 32 * j;
        const float av = sE[k];
        const float4 tv = pf[j];
        const float4 vv = __ldg(reinterpret_cast<const float4*>(Vbh + (size_t)k * Dn) + dq);
        acc.x += av * (tv.x + vv.x);
        acc.y += av * (tv.y + vv.y);
        acc.z += av * (tv.z + vv.z);
        acc.w += av * (tv.w + vv.w);
    }
#pragma unroll
    for (int j = 4; j < 8; j++) {
        const int k = k0 + 32 * j;
        const float av = sE[k];
        const float4 tv = __ldcs(reinterpret_cast<const float4*>(tmVq + (size_t)k * Dn) + dq);
        const float4 vv = __ldg (reinterpret_cast<const float4*>(Vbh  + (size_t)k * Dn) + dq);
        acc.x += av * (tv.x + vv.x);
        acc.y += av * (tv.y + vv.y);
        acc.z += av * (tv.z + vv.z);
        acc.w += av * (tv.w + vv.w);
    }
    reinterpret_cast<float4*>(red + k0 * Dn)[dq] = acc;
    __syncthreads();

    if (tid < Dn) {
        float xs = 0.f;
#pragma unroll
        for (int g = 0; g < 32; g++) xs += red[g * Dn + tid];
        __stcs(&x_out[((size_t)bh * Ln + q) * Dn + tid], xs);
    }
}

extern "C" void kernel_launch(void* const* d_in, const int* in_sizes, int n_in,
                              void* d_out, int out_size)
{
    const float* Q    = (const float*)d_in[0];
    const float* K    = (const float*)d_in[1];
    const float* V    = (const float*)d_in[2];
    const float* tmK  = (const float*)d_in[3];
    const float* tmV  = (const float*)d_in[4];
    const float* mask = (const float*)d_in[5];
    const unsigned char* pad = (const unsigned char*)d_in[6];

    float* out  = (float*)d_out;
    float* x    = out;                                // [B,H,L,D]
    float* attn = out + (size_t)Bz * Hn * Ln * Dn;    // [B,H,L,L]

    taa_kernel<<<Bz * Hn * Ln, 256>>>(Q, K, V, tmK, tmV, mask, pad, x, attn);
}